// round 7
// baseline (speedup 1.0000x reference)
#include <cuda_runtime.h>
#include <cuda_bf16.h>
#include <cstdint>
#include <cstddef>

#define BB 16
#define LL 4096
#define DD 64
#define TQ 128
#define TK 128
#define NQT (LL / TQ)          // 32
#define QSCALE (1.0f / (8.0f + 1e-6f))

// ---------------- global scratch (no cudaMalloc allowed) --------------------
__device__ __align__(16) __nv_bfloat16 g_Qhi[(size_t)BB * LL * DD];
__device__ __align__(16) __nv_bfloat16 g_Qlo[(size_t)BB * LL * DD];
__device__ __align__(16) __nv_bfloat16 g_Khi[(size_t)BB * LL * DD];
__device__ __align__(16) __nv_bfloat16 g_Klo[(size_t)BB * LL * DD];
__device__ __align__(16) __nv_bfloat16 g_Vhi[(size_t)BB * LL * DD];   // [b][key][d]
__device__ __align__(16) __nv_bfloat16 g_Vlo[(size_t)BB * LL * DD];

// ---------------- helpers ---------------------------------------------------
__device__ __forceinline__ uint32_t smem_u32(const void* p) {
    uint32_t a;
    asm("{ .reg .u64 t; cvta.to.shared.u64 t, %1; cvt.u32.u64 %0, t; }" : "=r"(a) : "l"(p));
    return a;
}

#define SW(o) ((o) ^ (((o) >> 3) & 0x70u))   // SW128 swizzle for 128B rows

#define CP_ASYNC16(sm, gm) \
    asm volatile("cp.async.cg.shared.global [%0], [%1], 16;" :: "r"(sm), "l"(gm) : "memory")
#define CP_COMMIT() asm volatile("cp.async.commit_group;" ::: "memory")
#define CP_WAIT0()  asm volatile("cp.async.wait_group 0;" ::: "memory")

__device__ __forceinline__ void ldm_x4(uint32_t* r, uint32_t addr) {
    asm volatile("ldmatrix.sync.aligned.m8n8.x4.shared.b16 {%0,%1,%2,%3}, [%4];"
                 : "=r"(r[0]), "=r"(r[1]), "=r"(r[2]), "=r"(r[3]) : "r"(addr));
}
__device__ __forceinline__ void ldm_x4t(uint32_t* r, uint32_t addr) {
    asm volatile("ldmatrix.sync.aligned.m8n8.x4.trans.shared.b16 {%0,%1,%2,%3}, [%4];"
                 : "=r"(r[0]), "=r"(r[1]), "=r"(r[2]), "=r"(r[3]) : "r"(addr));
}
__device__ __forceinline__ void mma16816(float* c, const uint32_t* a, const uint32_t* b) {
    asm volatile("mma.sync.aligned.m16n8k16.row.col.f32.bf16.bf16.f32 "
                 "{%0,%1,%2,%3}, {%4,%5,%6,%7}, {%8,%9}, {%0,%1,%2,%3};"
                 : "+f"(c[0]), "+f"(c[1]), "+f"(c[2]), "+f"(c[3])
                 : "r"(a[0]), "r"(a[1]), "r"(a[2]), "r"(a[3]), "r"(b[0]), "r"(b[1]));
}

__device__ __forceinline__ uint32_t pack_bf2(float a, float b) {
    __nv_bfloat16 h0 = __float2bfloat16(a), h1 = __float2bfloat16(b);
    return (uint32_t)__bfloat16_as_ushort(h0) |
           ((uint32_t)__bfloat16_as_ushort(h1) << 16);
}

// ---------------- prologue: split Q(prescaled)/K/V into bf16 hi/lo ----------
__global__ __launch_bounds__(256) void convert_split(
    const float* __restrict__ q, const float* __restrict__ k,
    const float* __restrict__ v)
{
    const size_t NU = (size_t)BB * LL * DD / 8;
    size_t u = (size_t)blockIdx.x * 256 + threadIdx.x;
    const float* src; __nv_bfloat16 *dh, *dl; float sc;
    if (u < NU)          { src = q; dh = g_Qhi; dl = g_Qlo; sc = QSCALE; }
    else if (u < 2 * NU) { u -= NU;     src = k; dh = g_Khi; dl = g_Klo; sc = 1.0f; }
    else                 { u -= 2 * NU; src = v; dh = g_Vhi; dl = g_Vlo; sc = 1.0f; }
    size_t e0 = u * 8;
    float4 a = *(const float4*)(src + e0);
    float4 c = *(const float4*)(src + e0 + 4);
    float x[8] = {a.x, a.y, a.z, a.w, c.x, c.y, c.z, c.w};
    uint32_t hw[4], lw[4];
    #pragma unroll
    for (int e = 0; e < 4; e++) {
        float x0 = x[2 * e] * sc, x1 = x[2 * e + 1] * sc;
        __nv_bfloat16 h0 = __float2bfloat16(x0), h1 = __float2bfloat16(x1);
        hw[e] = (uint32_t)__bfloat16_as_ushort(h0) |
                ((uint32_t)__bfloat16_as_ushort(h1) << 16);
        lw[e] = pack_bf2(x0 - __bfloat162float(h0), x1 - __bfloat162float(h1));
    }
    *(uint4*)(dh + e0) = make_uint4(hw[0], hw[1], hw[2], hw[3]);
    *(uint4*)(dl + e0) = make_uint4(lw[0], lw[1], lw[2], lw[3]);
}

// ---------------- smem layout (bytes) ---------------------------------------
// buf(i) at i*65536: [KH 16K][KL 16K][VH 16K][VL 16K]
#define OFF_KH 0u
#define OFF_KL 16384u
#define OFF_VH 32768u
#define OFF_VL 49152u
#define OFF_QH 131072u
#define OFF_QL 147456u
#define SMEM_TOTAL 163840

__device__ __forceinline__ void issue_kv(uint32_t sb, uint32_t buf, int b, int kt, int tid) {
    const size_t koff = ((size_t)b * LL + kt * TK) * DD;
    #pragma unroll
    for (int e = 0; e < 4; e++) {
        int u = e * 256 + tid;
        int r = u >> 3, du = u & 7;
        uint32_t so = SW((uint32_t)(r * 128 + du * 16));
        size_t go = koff + (size_t)r * DD + du * 8;
        CP_ASYNC16(sb + buf + OFF_KH + so, g_Khi + go);
        CP_ASYNC16(sb + buf + OFF_KL + so, g_Klo + go);
        CP_ASYNC16(sb + buf + OFF_VH + so, g_Vhi + go);
        CP_ASYNC16(sb + buf + OFF_VL + so, g_Vlo + go);
    }
}
__device__ __forceinline__ void issue_k(uint32_t sb, uint32_t buf, int b, int kt, int tid) {
    const size_t koff = ((size_t)b * LL + kt * TK) * DD;
    #pragma unroll
    for (int e = 0; e < 4; e++) {
        int u = e * 256 + tid;
        int r = u >> 3, du = u & 7;
        uint32_t so = SW((uint32_t)(r * 128 + du * 16));
        size_t go = koff + (size_t)r * DD + du * 8;
        CP_ASYNC16(sb + buf + OFF_KH + so, g_Khi + go);
        CP_ASYNC16(sb + buf + OFF_KL + so, g_Klo + go);
    }
}

// QK for one k-tile: S[16 x 128] into sc[16][4] C-fragments
__device__ __forceinline__ void qk_tile(float sc[16][4], uint32_t sb, uint32_t buf,
                                        uint32_t aqh[4][4], uint32_t aql[4][4], int l) {
    #pragma unroll
    for (int t = 0; t < 16; t++)
        #pragma unroll
        for (int e = 0; e < 4; e++) sc[t][e] = 0.f;
    #pragma unroll
    for (int t = 0; t < 16; t++) {
        #pragma unroll
        for (int cp = 0; cp < 2; cp++) {
            uint32_t off = (uint32_t)((t * 8 + (l & 7)) * 128 + cp * 64 + ((l >> 3) & 3) * 16);
            uint32_t bh[4], bl[4];
            ldm_x4(bh, sb + buf + OFF_KH + SW(off));
            ldm_x4(bl, sb + buf + OFF_KL + SW(off));
            mma16816(sc[t], aqh[2 * cp], bh);
            mma16816(sc[t], aqh[2 * cp], bl);
            mma16816(sc[t], aql[2 * cp], bh);
            mma16816(sc[t], aqh[2 * cp + 1], bh + 2);
            mma16816(sc[t], aqh[2 * cp + 1], bl + 2);
            mma16816(sc[t], aql[2 * cp + 1], bh + 2);
        }
    }
}

// ---------------- pass1: two-sweep flash attention on HMMA ------------------
// Sweep A: QK + exp + row-sums + PV (no attn store).
// Sweep B: recompute QK + exp, write normalized p once; fill causal tail.
__global__ __launch_bounds__(256, 1) void attn_pass1(
    const unsigned char* __restrict__ mask,
    float* __restrict__ out, float* __restrict__ attn)
{
    extern __shared__ char smem[];
    const uint32_t sb = smem_u32(smem);
    const int tid = threadIdx.x;
    const int w = tid >> 5, l = tid & 31;

    const int qt = (NQT - 1) - (int)blockIdx.x;   // long tiles first
    const int b = blockIdx.y;
    const int qbase = qt * TQ;

    // issue Q + KV(0)
    {
        const size_t qoff = ((size_t)b * LL + qbase) * DD;
        #pragma unroll
        for (int e = 0; e < 4; e++) {
            int u = e * 256 + tid;
            int r = u >> 3, du = u & 7;
            uint32_t so = SW((uint32_t)(r * 128 + du * 16));
            size_t go = qoff + (size_t)r * DD + du * 8;
            CP_ASYNC16(sb + OFF_QH + so, g_Qhi + go);
            CP_ASYNC16(sb + OFF_QL + so, g_Qlo + go);
        }
        issue_kv(sb, 0, b, 0, tid);
        CP_COMMIT();
        CP_WAIT0();
        __syncthreads();
    }

    // Q A-fragments (4 k16-chunks, hi+lo)
    uint32_t aqh[4][4], aql[4][4];
    {
        uint32_t rowoff = (uint32_t)((w * 16 + (l & 15)) * 128 + ((l >> 4) & 1) * 16);
        #pragma unroll
        for (int c = 0; c < 4; c++) {
            ldm_x4(aqh[c], sb + OFF_QH + SW(rowoff + c * 32));
            ldm_x4(aql[c], sb + OFF_QL + SW(rowoff + c * 32));
        }
    }

    const int r0 = w * 16 + (l >> 2);       // local q-row (and r0+8)
    const int qi0 = qbase + r0, qi1 = qi0 + 8;
    const bool m0 = mask[(size_t)b * LL + qi0] != 0;
    const bool m1 = mask[(size_t)b * LL + qi1] != 0;
    float la0 = 0.f, la1 = 0.f;
    float oc[8][4];
    #pragma unroll
    for (int t = 0; t < 8; t++)
        #pragma unroll
        for (int e = 0; e < 4; e++) oc[t][e] = 0.f;

    // ================= sweep A: l and O (no attn store) =================
    for (int kt = 0; kt <= qt; kt++) {
        const uint32_t buf = (uint32_t)(kt & 1) * 65536u;
        if (kt < qt) { issue_kv(sb, (uint32_t)((kt + 1) & 1) * 65536u, b, kt + 1, tid); CP_COMMIT(); }

        float sc[16][4];
        qk_tile(sc, sb, buf, aqh, aql, l);

        const int kbase = kt * TK;
        #pragma unroll
        for (int t = 0; t < 16; t++) {
            int key0 = kbase + t * 8 + 2 * (l & 3);
            float p0 = (!m0 && key0     <= qi0) ? __expf(sc[t][0]) : 0.f;
            float p1 = (!m0 && key0 + 1 <= qi0) ? __expf(sc[t][1]) : 0.f;
            float p2 = (!m1 && key0     <= qi1) ? __expf(sc[t][2]) : 0.f;
            float p3 = (!m1 && key0 + 1 <= qi1) ? __expf(sc[t][3]) : 0.f;
            sc[t][0] = p0; sc[t][1] = p1; sc[t][2] = p2; sc[t][3] = p3;
            la0 += p0 + p1;
            la1 += p2 + p3;
        }

        // PV: O += P * V (P A-frags rebuilt from C-frags, hi/lo split)
        #pragma unroll
        for (int c = 0; c < 8; c++) {
            uint32_t aPh[4], aPl[4];
            {
                float v0 = sc[2 * c][0], v1 = sc[2 * c][1];
                float v2 = sc[2 * c][2], v3 = sc[2 * c][3];
                float v4 = sc[2 * c + 1][0], v5 = sc[2 * c + 1][1];
                float v6 = sc[2 * c + 1][2], v7 = sc[2 * c + 1][3];
                aPh[0] = pack_bf2(v0, v1); aPh[1] = pack_bf2(v2, v3);
                aPh[2] = pack_bf2(v4, v5); aPh[3] = pack_bf2(v6, v7);
                float h;
                h = __bfloat162float(__float2bfloat16(v0)); float l0 = v0 - h;
                h = __bfloat162float(__float2bfloat16(v1)); float l1 = v1 - h;
                h = __bfloat162float(__float2bfloat16(v2)); float l2 = v2 - h;
                h = __bfloat162float(__float2bfloat16(v3)); float l3 = v3 - h;
                h = __bfloat162float(__float2bfloat16(v4)); float l4 = v4 - h;
                h = __bfloat162float(__float2bfloat16(v5)); float l5 = v5 - h;
                h = __bfloat162float(__float2bfloat16(v6)); float l6 = v6 - h;
                h = __bfloat162float(__float2bfloat16(v7)); float l7 = v7 - h;
                aPl[0] = pack_bf2(l0, l1); aPl[1] = pack_bf2(l2, l3);
                aPl[2] = pack_bf2(l4, l5); aPl[3] = pack_bf2(l6, l7);
            }
            #pragma unroll
            for (int dp = 0; dp < 4; dp++) {
                uint32_t voff = (uint32_t)((c * 16 + (l & 15)) * 128 + dp * 32 + ((l >> 4) & 1) * 16);
                uint32_t bvh[4], bvl[4];
                ldm_x4t(bvh, sb + buf + OFF_VH + SW(voff));
                ldm_x4t(bvl, sb + buf + OFF_VL + SW(voff));
                mma16816(oc[2 * dp], aPh, bvh);
                mma16816(oc[2 * dp], aPh, bvl);
                mma16816(oc[2 * dp], aPl, bvh);
                mma16816(oc[2 * dp + 1], aPh, bvh + 2);
                mma16816(oc[2 * dp + 1], aPh, bvl + 2);
                mma16816(oc[2 * dp + 1], aPl, bvh + 2);
            }
        }

        if (kt < qt) { CP_WAIT0(); __syncthreads(); }
    }

    // ---- row sums + O epilogue ----
    la0 += __shfl_xor_sync(0xffffffffu, la0, 1);
    la0 += __shfl_xor_sync(0xffffffffu, la0, 2);
    la1 += __shfl_xor_sync(0xffffffffu, la1, 1);
    la1 += __shfl_xor_sync(0xffffffffu, la1, 2);
    const float inv0 = (la0 > 0.f) ? (1.f / la0) : 0.f;
    const float inv1 = (la1 > 0.f) ? (1.f / la1) : 0.f;
    {
        float* orow0 = out + ((size_t)b * LL + qi0) * DD + 2 * (l & 3);
        float* orow1 = out + ((size_t)b * LL + qi1) * DD + 2 * (l & 3);
        #pragma unroll
        for (int t = 0; t < 8; t++) {
            *(float2*)(orow0 + t * 8) = make_float2(oc[t][0] * inv0, oc[t][1] * inv0);
            *(float2*)(orow1 + t * 8) = make_float2(oc[t][2] * inv1, oc[t][3] * inv1);
        }
    }

    // ================= sweep B: recompute S, write normalized p ==========
    const float uni = 1.0f / (float)LL;
    __syncthreads();                         // all warps done with smem K/V bufs
    issue_k(sb, 0, b, 0, tid);
    CP_COMMIT();
    CP_WAIT0();
    __syncthreads();

    for (int kt = 0; kt <= qt; kt++) {
        const uint32_t buf = (uint32_t)(kt & 1) * 65536u;
        if (kt < qt) { issue_k(sb, (uint32_t)((kt + 1) & 1) * 65536u, b, kt + 1, tid); CP_COMMIT(); }

        float sc[16][4];
        qk_tile(sc, sb, buf, aqh, aql, l);

        const int kbase = kt * TK;
        float* arow0 = attn + ((size_t)b * LL + qi0) * LL + kbase + 2 * (l & 3);
        float* arow1 = attn + ((size_t)b * LL + qi1) * LL + kbase + 2 * (l & 3);
        #pragma unroll
        for (int t = 0; t < 16; t++) {
            int key0 = kbase + t * 8 + 2 * (l & 3);
            float p0 = (key0     <= qi0) ? __expf(sc[t][0]) * inv0 : 0.f;
            float p1 = (key0 + 1 <= qi0) ? __expf(sc[t][1]) * inv0 : 0.f;
            float p2 = (key0     <= qi1) ? __expf(sc[t][2]) * inv1 : 0.f;
            float p3 = (key0 + 1 <= qi1) ? __expf(sc[t][3]) * inv1 : 0.f;
            if (m0) { p0 = uni; p1 = uni; }
            if (m1) { p2 = uni; p3 = uni; }
            *(float2*)(arow0 + t * 8) = make_float2(p0, p1);
            *(float2*)(arow1 + t * 8) = make_float2(p2, p3);
        }

        if (kt < qt) { CP_WAIT0(); __syncthreads(); }
    }

    // ---- causal tail fill: cols [limit, LL) -> 0 (or uni for masked rows) --
    {
        const int limit = (qt + 1) * TK;
        #pragma unroll 1
        for (int rr = 0; rr < 16; rr++) {
            const int row = w * 16 + rr;
            const int qi = qbase + row;
            const float fv = (mask[(size_t)b * LL + qi] != 0) ? uni : 0.f;
            const float4 f4 = make_float4(fv, fv, fv, fv);
            float* ap = attn + ((size_t)b * LL + qi) * LL;
            for (int c = limit + l * 4; c < LL; c += 128) *(float4*)(ap + c) = f4;
        }
    }
}

// ---------------- pass3: masked rows -> uniform mean of V -------------------
__global__ __launch_bounds__(64) void attn_pass3(
    const unsigned char* __restrict__ mask,
    const float* __restrict__ v, float* __restrict__ out)
{
    const int row = blockIdx.x * 64 + threadIdx.x;   // b*L + i
    const bool m = mask[row] != 0;
    if (!__syncthreads_or(m)) return;                // fast path: no masked rows
    if (!m) return;
    const int b = row >> 12;
    const float* vb = v + (size_t)b * LL * DD;
    for (int d = 0; d < DD; d++) {
        float s = 0.f;
        for (int kk = 0; kk < LL; kk++) s += vb[(size_t)kk * DD + d];
        out[(size_t)row * DD + d] = s * (1.0f / (float)LL);
    }
}

extern "C" void kernel_launch(void* const* d_in, const int* in_sizes, int n_in,
                              void* d_out, int out_size)
{
    (void)in_sizes; (void)n_in; (void)out_size;
    const float* q = (const float*)d_in[0];
    const float* k = (const float*)d_in[1];
    const float* v = (const float*)d_in[2];
    const unsigned char* mask = (const unsigned char*)d_in[3];

    float* out = (float*)d_out;
    float* attn = out + (size_t)BB * LL * DD;

    cudaFuncSetAttribute(attn_pass1, cudaFuncAttributeMaxDynamicSharedMemorySize, SMEM_TOTAL);

    const int NCONV = (int)(3 * (size_t)BB * LL * DD / 8 / 256);  // 6144 blocks
    convert_split<<<NCONV, 256>>>(q, k, v);
    attn_pass1<<<dim3(NQT, BB), 256, SMEM_TOTAL>>>(mask, out, attn);
    attn_pass3<<<BB * LL / 64, 64>>>(mask, v, out);
}

// round 11
// speedup vs baseline: 1.1994x; 1.1994x over previous
#include <cuda_runtime.h>
#include <cuda_bf16.h>
#include <cuda_fp16.h>
#include <cstdint>
#include <cstddef>

#define BB 16
#define LL 4096
#define DD 64
#define TQ 128
#define TK 128
#define NQT (LL / TQ)          // 32
#define QSCALE (1.0f / (8.0f + 1e-6f))

// ---------------- global scratch (no cudaMalloc allowed) --------------------
__device__ __align__(16) __nv_bfloat16 g_Qhi[(size_t)BB * LL * DD];
__device__ __align__(16) __nv_bfloat16 g_Qlo[(size_t)BB * LL * DD];
__device__ __align__(16) __nv_bfloat16 g_Khi[(size_t)BB * LL * DD];
__device__ __align__(16) __nv_bfloat16 g_Klo[(size_t)BB * LL * DD];
__device__ __align__(16) __nv_bfloat16 g_Vhi[(size_t)BB * LL * DD];   // [b][key][d]
__device__ __align__(16) __nv_bfloat16 g_Vlo[(size_t)BB * LL * DD];
__device__ __align__(16) __half g_pattn[(size_t)BB * LL * LL];        // unnormalized p, fp16
__device__ float g_lsum[BB * LL];

// ---------------- helpers ---------------------------------------------------
__device__ __forceinline__ uint32_t smem_u32(const void* p) {
    uint32_t a;
    asm("{ .reg .u64 t; cvta.to.shared.u64 t, %1; cvt.u32.u64 %0, t; }" : "=r"(a) : "l"(p));
    return a;
}

#define SW(o) ((o) ^ (((o) >> 3) & 0x70u))   // SW128 swizzle for 128B rows

#define CP_ASYNC16(sm, gm) \
    asm volatile("cp.async.cg.shared.global [%0], [%1], 16;" :: "r"(sm), "l"(gm) : "memory")
#define CP_COMMIT() asm volatile("cp.async.commit_group;" ::: "memory")
#define CP_WAIT0()  asm volatile("cp.async.wait_group 0;" ::: "memory")

__device__ __forceinline__ void ldm_x4(uint32_t* r, uint32_t addr) {
    asm volatile("ldmatrix.sync.aligned.m8n8.x4.shared.b16 {%0,%1,%2,%3}, [%4];"
                 : "=r"(r[0]), "=r"(r[1]), "=r"(r[2]), "=r"(r[3]) : "r"(addr));
}
__device__ __forceinline__ void ldm_x4t(uint32_t* r, uint32_t addr) {
    asm volatile("ldmatrix.sync.aligned.m8n8.x4.trans.shared.b16 {%0,%1,%2,%3}, [%4];"
                 : "=r"(r[0]), "=r"(r[1]), "=r"(r[2]), "=r"(r[3]) : "r"(addr));
}
__device__ __forceinline__ void mma16816(float* c, const uint32_t* a, const uint32_t* b) {
    asm volatile("mma.sync.aligned.m16n8k16.row.col.f32.bf16.bf16.f32 "
                 "{%0,%1,%2,%3}, {%4,%5,%6,%7}, {%8,%9}, {%0,%1,%2,%3};"
                 : "+f"(c[0]), "+f"(c[1]), "+f"(c[2]), "+f"(c[3])
                 : "r"(a[0]), "r"(a[1]), "r"(a[2]), "r"(a[3]), "r"(b[0]), "r"(b[1]));
}

// pack two floats as bf16x2 (a -> low half, b -> high half), round-to-nearest
__device__ __forceinline__ uint32_t cvt_bf2(float a, float b) {
    uint32_t r;
    asm("cvt.rn.bf16x2.f32 %0, %1, %2;" : "=r"(r) : "f"(b), "f"(a));
    return r;
}
// pack two floats as f16x2 (a -> low half, b -> high half), round-to-nearest
__device__ __forceinline__ uint32_t cvt_h2(float a, float b) {
    uint32_t r;
    asm("cvt.rn.f16x2.f32 %0, %1, %2;" : "=r"(r) : "f"(b), "f"(a));
    return r;
}

// ---------------- prologue: split Q(prescaled)/K/V into bf16 hi/lo ----------
__global__ __launch_bounds__(256) void convert_split(
    const float* __restrict__ q, const float* __restrict__ k,
    const float* __restrict__ v)
{
    const size_t NU = (size_t)BB * LL * DD / 8;
    size_t u = (size_t)blockIdx.x * 256 + threadIdx.x;
    const float* src; __nv_bfloat16 *dh, *dl; float sc;
    if (u < NU)          { src = q; dh = g_Qhi; dl = g_Qlo; sc = QSCALE; }
    else if (u < 2 * NU) { u -= NU;     src = k; dh = g_Khi; dl = g_Klo; sc = 1.0f; }
    else                 { u -= 2 * NU; src = v; dh = g_Vhi; dl = g_Vlo; sc = 1.0f; }
    size_t e0 = u * 8;
    float4 a = *(const float4*)(src + e0);
    float4 c = *(const float4*)(src + e0 + 4);
    float x[8] = {a.x, a.y, a.z, a.w, c.x, c.y, c.z, c.w};
    uint32_t hw[4], lw[4];
    #pragma unroll
    for (int e = 0; e < 4; e++) {
        float x0 = x[2 * e] * sc, x1 = x[2 * e + 1] * sc;
        uint32_t h = cvt_bf2(x0, x1);
        float h0 = __uint_as_float(h << 16);
        float h1 = __uint_as_float(h & 0xFFFF0000u);
        hw[e] = h;
        lw[e] = cvt_bf2(x0 - h0, x1 - h1);
    }
    *(uint4*)(dh + e0) = make_uint4(hw[0], hw[1], hw[2], hw[3]);
    *(uint4*)(dl + e0) = make_uint4(lw[0], lw[1], lw[2], lw[3]);
}

// ---------------- smem layout (bytes) ---------------------------------------
// buf(i) at i*65536: [KH 16K][KL 16K][VH 16K][VL 16K]
#define OFF_KH 0u
#define OFF_KL 16384u
#define OFF_VH 32768u
#define OFF_VL 49152u
#define OFF_QH 131072u
#define OFF_QL 147456u
#define SMEM_TOTAL 163840

__device__ __forceinline__ void issue_kv(uint32_t sb, uint32_t buf, int b, int kt, int tid) {
    const size_t koff = ((size_t)b * LL + kt * TK) * DD;
    #pragma unroll
    for (int e = 0; e < 4; e++) {
        int u = e * 256 + tid;
        int r = u >> 3, du = u & 7;
        uint32_t so = SW((uint32_t)(r * 128 + du * 16));
        size_t go = koff + (size_t)r * DD + du * 8;
        CP_ASYNC16(sb + buf + OFF_KH + so, g_Khi + go);
        CP_ASYNC16(sb + buf + OFF_KL + so, g_Klo + go);
        CP_ASYNC16(sb + buf + OFF_VH + so, g_Vhi + go);
        CP_ASYNC16(sb + buf + OFF_VL + so, g_Vlo + go);
    }
}

// ---------------- pass1: flash-style causal attention on HMMA ---------------
__global__ __launch_bounds__(256, 1) void attn_pass1(
    const unsigned char* __restrict__ mask, float* __restrict__ out)
{
    extern __shared__ char smem[];
    const uint32_t sb = smem_u32(smem);
    const int tid = threadIdx.x;
    const int w = tid >> 5, l = tid & 31;

    const int qt = (NQT - 1) - (int)blockIdx.x;   // long tiles first
    const int b = blockIdx.y;
    const int qbase = qt * TQ;

    // issue Q + KV(0)
    {
        const size_t qoff = ((size_t)b * LL + qbase) * DD;
        #pragma unroll
        for (int e = 0; e < 4; e++) {
            int u = e * 256 + tid;
            int r = u >> 3, du = u & 7;
            uint32_t so = SW((uint32_t)(r * 128 + du * 16));
            size_t go = qoff + (size_t)r * DD + du * 8;
            CP_ASYNC16(sb + OFF_QH + so, g_Qhi + go);
            CP_ASYNC16(sb + OFF_QL + so, g_Qlo + go);
        }
        issue_kv(sb, 0, b, 0, tid);
        CP_COMMIT();
        CP_WAIT0();
        __syncthreads();
    }

    // Q A-fragments (4 k16-chunks, hi+lo)
    uint32_t aqh[4][4], aql[4][4];
    {
        uint32_t rowoff = (uint32_t)((w * 16 + (l & 15)) * 128 + ((l >> 4) & 1) * 16);
        #pragma unroll
        for (int c = 0; c < 4; c++) {
            ldm_x4(aqh[c], sb + OFF_QH + SW(rowoff + c * 32));
            ldm_x4(aql[c], sb + OFF_QL + SW(rowoff + c * 32));
        }
    }

    const int r0 = w * 16 + (l >> 2);       // local q-row (and r0+8)
    const int qi0 = qbase + r0, qi1 = qi0 + 8;
    const bool m0 = mask[(size_t)b * LL + qi0] != 0;
    const bool m1 = mask[(size_t)b * LL + qi1] != 0;
    float la0 = 0.f, la1 = 0.f;
    float oc[8][4];
    #pragma unroll
    for (int t = 0; t < 8; t++)
        #pragma unroll
        for (int e = 0; e < 4; e++) oc[t][e] = 0.f;

    for (int kt = 0; kt <= qt; kt++) {
        const uint32_t buf = (uint32_t)(kt & 1) * 65536u;
        if (kt < qt) { issue_kv(sb, (uint32_t)((kt + 1) & 1) * 65536u, b, kt + 1, tid); CP_COMMIT(); }

        // ---- QK: S[16 x 128] in C-frags sc[16][4] ----
        float sc[16][4];
        #pragma unroll
        for (int t = 0; t < 16; t++)
            #pragma unroll
            for (int e = 0; e < 4; e++) sc[t][e] = 0.f;

        #pragma unroll
        for (int t = 0; t < 16; t++) {
            #pragma unroll
            for (int cp = 0; cp < 2; cp++) {
                uint32_t off = (uint32_t)((t * 8 + (l & 7)) * 128 + cp * 64 + ((l >> 3) & 3) * 16);
                uint32_t bh[4], bl[4];
                ldm_x4(bh, sb + buf + OFF_KH + SW(off));
                ldm_x4(bl, sb + buf + OFF_KL + SW(off));
                mma16816(sc[t], aqh[2 * cp], bh);
                mma16816(sc[t], aqh[2 * cp], bl);
                mma16816(sc[t], aql[2 * cp], bh);
                mma16816(sc[t], aqh[2 * cp + 1], bh + 2);
                mma16816(sc[t], aqh[2 * cp + 1], bl + 2);
                mma16816(sc[t], aql[2 * cp + 1], bh + 2);
            }
        }

        // ---- exp + mask + store fp16 p to g_pattn + row-sum partials ----
        const int kbase = kt * TK;
        __half* pr0 = g_pattn + ((size_t)b * LL + qi0) * LL + kbase + 2 * (l & 3);
        __half* pr1 = g_pattn + ((size_t)b * LL + qi1) * LL + kbase + 2 * (l & 3);
        #pragma unroll
        for (int t = 0; t < 16; t++) {
            int key0 = kbase + t * 8 + 2 * (l & 3);
            float p0 = (!m0 && key0     <= qi0) ? __expf(sc[t][0]) : 0.f;
            float p1 = (!m0 && key0 + 1 <= qi0) ? __expf(sc[t][1]) : 0.f;
            float p2 = (!m1 && key0     <= qi1) ? __expf(sc[t][2]) : 0.f;
            float p3 = (!m1 && key0 + 1 <= qi1) ? __expf(sc[t][3]) : 0.f;
            sc[t][0] = p0; sc[t][1] = p1; sc[t][2] = p2; sc[t][3] = p3;
            *(uint32_t*)(pr0 + t * 8) = cvt_h2(p0, p1);
            *(uint32_t*)(pr1 + t * 8) = cvt_h2(p2, p3);
            la0 += p0 + p1;
            la1 += p2 + p3;
        }

        // ---- PV: O += P * V (hi = rn-bf16 of p; lo = p - hi) ----
        #pragma unroll
        for (int c = 0; c < 8; c++) {
            uint32_t aPh[4], aPl[4];
            #pragma unroll
            for (int pi = 0; pi < 4; pi++) {
                float x0 = sc[2 * c + (pi >> 1)][(pi & 1) * 2];
                float x1 = sc[2 * c + (pi >> 1)][(pi & 1) * 2 + 1];
                uint32_t h = cvt_bf2(x0, x1);
                aPh[pi] = h;
                float h0 = __uint_as_float(h << 16);
                float h1 = __uint_as_float(h & 0xFFFF0000u);
                aPl[pi] = cvt_bf2(x0 - h0, x1 - h1);
            }
            #pragma unroll
            for (int dp = 0; dp < 4; dp++) {
                uint32_t voff = (uint32_t)((c * 16 + (l & 15)) * 128 + dp * 32 + ((l >> 4) & 1) * 16);
                uint32_t bvh[4], bvl[4];
                ldm_x4t(bvh, sb + buf + OFF_VH + SW(voff));
                ldm_x4t(bvl, sb + buf + OFF_VL + SW(voff));
                mma16816(oc[2 * dp], aPh, bvh);
                mma16816(oc[2 * dp], aPh, bvl);
                mma16816(oc[2 * dp], aPl, bvh);
                mma16816(oc[2 * dp + 1], aPh, bvh + 2);
                mma16816(oc[2 * dp + 1], aPh, bvl + 2);
                mma16816(oc[2 * dp + 1], aPl, bvh + 2);
            }
        }

        if (kt < qt) { CP_WAIT0(); __syncthreads(); }
    }

    // ---- row sums, O epilogue ----
    la0 += __shfl_xor_sync(0xffffffffu, la0, 1);
    la0 += __shfl_xor_sync(0xffffffffu, la0, 2);
    la1 += __shfl_xor_sync(0xffffffffu, la1, 1);
    la1 += __shfl_xor_sync(0xffffffffu, la1, 2);
    if ((l & 3) == 0) {
        g_lsum[(size_t)b * LL + qi0] = la0;
        g_lsum[(size_t)b * LL + qi1] = la1;
    }
    const float inv0 = (la0 > 0.f) ? (1.f / la0) : 0.f;
    const float inv1 = (la1 > 0.f) ? (1.f / la1) : 0.f;
    float* orow0 = out + ((size_t)b * LL + qi0) * DD + 2 * (l & 3);
    float* orow1 = out + ((size_t)b * LL + qi1) * DD + 2 * (l & 3);
    #pragma unroll
    for (int t = 0; t < 8; t++) {
        *(float2*)(orow0 + t * 8) = make_float2(oc[t][0] * inv0, oc[t][1] * inv0);
        *(float2*)(orow1 + t * 8) = make_float2(oc[t][2] * inv1, oc[t][3] * inv1);
    }
}

// ---------------- pass2: fp16 p -> normalized fp32 attn, zero tail ----------
__global__ __launch_bounds__(256) void attn_pass2(
    const unsigned char* __restrict__ mask, float* __restrict__ attn)
{
    const int row = blockIdx.x;            // b*L + i
    const int i = row & (LL - 1);
    const bool m = mask[row] != 0;
    const float lsum = g_lsum[row];
    const float inv = (lsum > 0.f) ? (1.f / lsum) : 0.f;
    const int limit = ((i >> 7) + 1) << 7;  // cols written by pass 1 (128-tiles)
    const __half* sp = g_pattn + (size_t)row * LL;
    float* ap = attn + (size_t)row * LL;
    const float uni = 1.0f / (float)LL;
    const float4 zf = make_float4(0.f, 0.f, 0.f, 0.f);
    const float4 uf = make_float4(uni, uni, uni, uni);

    for (int j = threadIdx.x * 4; j < LL; j += 256 * 4) {
        float4 wv;
        if (m) {
            wv = uf;
        } else if (j < limit) {
            uint2 r = *(const uint2*)(sp + j);
            float2 f0 = __half22float2(*reinterpret_cast<__half2*>(&r.x));
            float2 f1 = __half22float2(*reinterpret_cast<__half2*>(&r.y));
            wv = make_float4(f0.x * inv, f0.y * inv, f1.x * inv, f1.y * inv);
        } else {
            wv = zf;
        }
        *(float4*)(ap + j) = wv;
    }
}

// ---------------- pass3: masked rows -> uniform mean of V -------------------
__global__ __launch_bounds__(64) void attn_pass3(
    const unsigned char* __restrict__ mask,
    const float* __restrict__ v, float* __restrict__ out)
{
    const int row = blockIdx.x * 64 + threadIdx.x;   // b*L + i
    const bool m = mask[row] != 0;
    if (!__syncthreads_or(m)) return;                // fast path: no masked rows
    if (!m) return;
    const int b = row >> 12;
    const float* vb = v + (size_t)b * LL * DD;
    for (int d = 0; d < DD; d++) {
        float s = 0.f;
        for (int kk = 0; kk < LL; kk++) s += vb[(size_t)kk * DD + d];
        out[(size_t)row * DD + d] = s * (1.0f / (float)LL);
    }
}

extern "C" void kernel_launch(void* const* d_in, const int* in_sizes, int n_in,
                              void* d_out, int out_size)
{
    (void)in_sizes; (void)n_in; (void)out_size;
    const float* q = (const float*)d_in[0];
    const float* k = (const float*)d_in[1];
    const float* v = (const float*)d_in[2];
    const unsigned char* mask = (const unsigned char*)d_in[3];

    float* out = (float*)d_out;
    float* attn = out + (size_t)BB * LL * DD;

    cudaFuncSetAttribute(attn_pass1, cudaFuncAttributeMaxDynamicSharedMemorySize, SMEM_TOTAL);

    const int NCONV = (int)(3 * (size_t)BB * LL * DD / 8 / 256);  // 6144 blocks
    convert_split<<<NCONV, 256>>>(q, k, v);
    attn_pass1<<<dim3(NQT, BB), 256, SMEM_TOTAL>>>(mask, out);
    attn_pass2<<<BB * LL, 256>>>(mask, attn);
    attn_pass3<<<BB * LL / 64, 64>>>(mask, v, out);
}

// round 12
// speedup vs baseline: 1.6382x; 1.3658x over previous
#include <cuda_runtime.h>
#include <cuda_bf16.h>
#include <cuda_fp16.h>
#include <cstdint>
#include <cstddef>

#define BB 16
#define LL 4096
#define DD 64
#define TQ 128
#define TK 128
#define NQT (LL / TQ)          // 32
#define QSCALE (1.0f / (8.0f + 1e-6f))

// ---------------- global scratch (no cudaMalloc allowed) --------------------
__device__ __align__(16) __half g_Qh[(size_t)BB * LL * DD];    // Q/8.000001, fp16
__device__ __align__(16) __half g_Kh[(size_t)BB * LL * DD];    // K, fp16
__device__ __align__(16) __half g_Vh[(size_t)BB * LL * DD];    // V, fp16 [b][key][d]
__device__ __align__(16) __half g_pattn[(size_t)BB * LL * LL]; // unnormalized p, fp16
__device__ float g_lsum[BB * LL];

// ---------------- helpers ---------------------------------------------------
__device__ __forceinline__ uint32_t smem_u32(const void* p) {
    uint32_t a;
    asm("{ .reg .u64 t; cvta.to.shared.u64 t, %1; cvt.u32.u64 %0, t; }" : "=r"(a) : "l"(p));
    return a;
}

#define SW(o) ((o) ^ (((o) >> 3) & 0x70u))   // SW128 swizzle for 128B rows

#define CP_ASYNC16(sm, gm) \
    asm volatile("cp.async.cg.shared.global [%0], [%1], 16;" :: "r"(sm), "l"(gm) : "memory")
#define CP_COMMIT() asm volatile("cp.async.commit_group;" ::: "memory")
#define CP_WAIT0()  asm volatile("cp.async.wait_group 0;" ::: "memory")

__device__ __forceinline__ void ldm_x4(uint32_t* r, uint32_t addr) {
    asm volatile("ldmatrix.sync.aligned.m8n8.x4.shared.b16 {%0,%1,%2,%3}, [%4];"
                 : "=r"(r[0]), "=r"(r[1]), "=r"(r[2]), "=r"(r[3]) : "r"(addr));
}
__device__ __forceinline__ void ldm_x4t(uint32_t* r, uint32_t addr) {
    asm volatile("ldmatrix.sync.aligned.m8n8.x4.trans.shared.b16 {%0,%1,%2,%3}, [%4];"
                 : "=r"(r[0]), "=r"(r[1]), "=r"(r[2]), "=r"(r[3]) : "r"(addr));
}
// fp16 x fp16 -> fp32 accum
__device__ __forceinline__ void mma_h(float* c, const uint32_t* a, const uint32_t* b) {
    asm volatile("mma.sync.aligned.m16n8k16.row.col.f32.f16.f16.f32 "
                 "{%0,%1,%2,%3}, {%4,%5,%6,%7}, {%8,%9}, {%0,%1,%2,%3};"
                 : "+f"(c[0]), "+f"(c[1]), "+f"(c[2]), "+f"(c[3])
                 : "r"(a[0]), "r"(a[1]), "r"(a[2]), "r"(a[3]), "r"(b[0]), "r"(b[1]));
}

// pack two floats as f16x2 (a -> low half, b -> high half), round-to-nearest
__device__ __forceinline__ uint32_t cvt_h2(float a, float b) {
    uint32_t r;
    asm("cvt.rn.f16x2.f32 %0, %1, %2;" : "=r"(r) : "f"(b), "f"(a));
    return r;
}

// ---------------- prologue: Q(prescaled)/K/V -> fp16 ------------------------
__global__ __launch_bounds__(256) void convert_h(
    const float* __restrict__ q, const float* __restrict__ k,
    const float* __restrict__ v)
{
    const size_t NU = (size_t)BB * LL * DD / 8;
    size_t u = (size_t)blockIdx.x * 256 + threadIdx.x;
    const float* src; __half* dst; float sc;
    if (u < NU)          { src = q; dst = g_Qh; sc = QSCALE; }
    else if (u < 2 * NU) { u -= NU;     src = k; dst = g_Kh; sc = 1.0f; }
    else                 { u -= 2 * NU; src = v; dst = g_Vh; sc = 1.0f; }
    size_t e0 = u * 8;
    float4 a = *(const float4*)(src + e0);
    float4 c = *(const float4*)(src + e0 + 4);
    uint4 o;
    o.x = cvt_h2(a.x * sc, a.y * sc);
    o.y = cvt_h2(a.z * sc, a.w * sc);
    o.z = cvt_h2(c.x * sc, c.y * sc);
    o.w = cvt_h2(c.z * sc, c.w * sc);
    *(uint4*)(dst + e0) = o;
}

// ---------------- smem layout (bytes) ---------------------------------------
// buf(i) at i*32768: [K 16K][V 16K]; Q at 65536
#define OFF_K 0u
#define OFF_V 16384u
#define OFF_Q 65536u
#define SMEM_TOTAL 81920

__device__ __forceinline__ void issue_kv(uint32_t sb, uint32_t buf, int b, int kt, int tid) {
    const size_t koff = ((size_t)b * LL + kt * TK) * DD;
    #pragma unroll
    for (int e = 0; e < 4; e++) {
        int u = e * 256 + tid;
        int r = u >> 3, du = u & 7;
        uint32_t so = SW((uint32_t)(r * 128 + du * 16));
        size_t go = koff + (size_t)r * DD + du * 8;
        CP_ASYNC16(sb + buf + OFF_K + so, g_Kh + go);
        CP_ASYNC16(sb + buf + OFF_V + so, g_Vh + go);
    }
}

// ---------------- pass1: flash-style causal attention, fp16 HMMA ------------
__global__ __launch_bounds__(256, 1) void attn_pass1(
    const unsigned char* __restrict__ mask, float* __restrict__ out)
{
    extern __shared__ char smem[];
    const uint32_t sb = smem_u32(smem);
    const int tid = threadIdx.x;
    const int w = tid >> 5, l = tid & 31;

    const int qt = (NQT - 1) - (int)blockIdx.x;   // long tiles first
    const int b = blockIdx.y;
    const int qbase = qt * TQ;

    // issue Q + KV(0)
    {
        const size_t qoff = ((size_t)b * LL + qbase) * DD;
        #pragma unroll
        for (int e = 0; e < 4; e++) {
            int u = e * 256 + tid;
            int r = u >> 3, du = u & 7;
            uint32_t so = SW((uint32_t)(r * 128 + du * 16));
            CP_ASYNC16(sb + OFF_Q + so, g_Qh + qoff + (size_t)r * DD + du * 8);
        }
        issue_kv(sb, 0, b, 0, tid);
        CP_COMMIT();
        CP_WAIT0();
        __syncthreads();
    }

    // Q A-fragments (4 k16-chunks)
    uint32_t aq[4][4];
    {
        uint32_t rowoff = (uint32_t)((w * 16 + (l & 15)) * 128 + ((l >> 4) & 1) * 16);
        #pragma unroll
        for (int c = 0; c < 4; c++)
            ldm_x4(aq[c], sb + OFF_Q + SW(rowoff + c * 32));
    }

    const int r0 = w * 16 + (l >> 2);       // local q-row (and r0+8)
    const int qi0 = qbase + r0, qi1 = qi0 + 8;
    const bool m0 = mask[(size_t)b * LL + qi0] != 0;
    const bool m1 = mask[(size_t)b * LL + qi1] != 0;
    float la0 = 0.f, la1 = 0.f;
    float oc[8][4];
    #pragma unroll
    for (int t = 0; t < 8; t++)
        #pragma unroll
        for (int e = 0; e < 4; e++) oc[t][e] = 0.f;

    for (int kt = 0; kt <= qt; kt++) {
        const uint32_t buf = (uint32_t)(kt & 1) * 32768u;
        if (kt < qt) { issue_kv(sb, (uint32_t)((kt + 1) & 1) * 32768u, b, kt + 1, tid); CP_COMMIT(); }

        // ---- QK: S[16 x 128] in C-frags sc[16][4] ----
        float sc[16][4];
        #pragma unroll
        for (int t = 0; t < 16; t++)
            #pragma unroll
            for (int e = 0; e < 4; e++) sc[t][e] = 0.f;

        #pragma unroll
        for (int t = 0; t < 16; t++) {
            #pragma unroll
            for (int cp = 0; cp < 2; cp++) {
                uint32_t off = (uint32_t)((t * 8 + (l & 7)) * 128 + cp * 64 + ((l >> 3) & 3) * 16);
                uint32_t bk[4];
                ldm_x4(bk, sb + buf + OFF_K + SW(off));
                mma_h(sc[t], aq[2 * cp], bk);
                mma_h(sc[t], aq[2 * cp + 1], bk + 2);
            }
        }

        // ---- exp + mask + store fp16 p + keep packed P frags ----
        const int kbase = kt * TK;
        __half* pr0 = g_pattn + ((size_t)b * LL + qi0) * LL + kbase + 2 * (l & 3);
        __half* pr1 = g_pattn + ((size_t)b * LL + qi1) * LL + kbase + 2 * (l & 3);
        uint32_t u0[16], u1[16];            // packed p: rows (r0, r0+8) per n8 tile
        #pragma unroll
        for (int t = 0; t < 16; t++) {
            int key0 = kbase + t * 8 + 2 * (l & 3);
            float p0 = (!m0 && key0     <= qi0) ? __expf(sc[t][0]) : 0.f;
            float p1 = (!m0 && key0 + 1 <= qi0) ? __expf(sc[t][1]) : 0.f;
            float p2 = (!m1 && key0     <= qi1) ? __expf(sc[t][2]) : 0.f;
            float p3 = (!m1 && key0 + 1 <= qi1) ? __expf(sc[t][3]) : 0.f;
            u0[t] = cvt_h2(p0, p1);
            u1[t] = cvt_h2(p2, p3);
            *(uint32_t*)(pr0 + t * 8) = u0[t];
            *(uint32_t*)(pr1 + t * 8) = u1[t];
            la0 += p0 + p1;
            la1 += p2 + p3;
        }

        // ---- PV: O += P * V (P frags = stored fp16 bits, exactly) ----
        #pragma unroll
        for (int c = 0; c < 8; c++) {
            uint32_t aP[4] = {u0[2 * c], u1[2 * c], u0[2 * c + 1], u1[2 * c + 1]};
            #pragma unroll
            for (int dp = 0; dp < 4; dp++) {
                uint32_t voff = (uint32_t)((c * 16 + (l & 15)) * 128 + dp * 32 + ((l >> 4) & 1) * 16);
                uint32_t bv[4];
                ldm_x4t(bv, sb + buf + OFF_V + SW(voff));
                mma_h(oc[2 * dp], aP, bv);
                mma_h(oc[2 * dp + 1], aP, bv + 2);
            }
        }

        if (kt < qt) { CP_WAIT0(); __syncthreads(); }
    }

    // ---- row sums, O epilogue ----
    la0 += __shfl_xor_sync(0xffffffffu, la0, 1);
    la0 += __shfl_xor_sync(0xffffffffu, la0, 2);
    la1 += __shfl_xor_sync(0xffffffffu, la1, 1);
    la1 += __shfl_xor_sync(0xffffffffu, la1, 2);
    if ((l & 3) == 0) {
        g_lsum[(size_t)b * LL + qi0] = la0;
        g_lsum[(size_t)b * LL + qi1] = la1;
    }
    const float inv0 = (la0 > 0.f) ? (1.f / la0) : 0.f;
    const float inv1 = (la1 > 0.f) ? (1.f / la1) : 0.f;
    float* orow0 = out + ((size_t)b * LL + qi0) * DD + 2 * (l & 3);
    float* orow1 = out + ((size_t)b * LL + qi1) * DD + 2 * (l & 3);
    #pragma unroll
    for (int t = 0; t < 8; t++) {
        *(float2*)(orow0 + t * 8) = make_float2(oc[t][0] * inv0, oc[t][1] * inv0);
        *(float2*)(orow1 + t * 8) = make_float2(oc[t][2] * inv1, oc[t][3] * inv1);
    }
}

// ---------------- pass2: fp16 p -> normalized fp32 attn, zero tail ----------
__global__ __launch_bounds__(256) void attn_pass2(
    const unsigned char* __restrict__ mask, float* __restrict__ attn)
{
    const int row = blockIdx.x;            // b*L + i
    const int i = row & (LL - 1);
    const bool m = mask[row] != 0;
    const float lsum = g_lsum[row];
    const float inv = (lsum > 0.f) ? (1.f / lsum) : 0.f;
    const int limit = ((i >> 7) + 1) << 7;  // cols written by pass 1 (128-tiles)
    const __half* sp = g_pattn + (size_t)row * LL;
    float* ap = attn + (size_t)row * LL;
    const float uni = 1.0f / (float)LL;
    const float4 zf = make_float4(0.f, 0.f, 0.f, 0.f);
    const float4 uf = make_float4(uni, uni, uni, uni);

    for (int j = threadIdx.x * 4; j < LL; j += 256 * 4) {
        float4 wv;
        if (m) {
            wv = uf;
        } else if (j < limit) {
            uint2 r = *(const uint2*)(sp + j);
            float2 f0 = __half22float2(*reinterpret_cast<__half2*>(&r.x));
            float2 f1 = __half22float2(*reinterpret_cast<__half2*>(&r.y));
            wv = make_float4(f0.x * inv, f0.y * inv, f1.x * inv, f1.y * inv);
        } else {
            wv = zf;
        }
        *(float4*)(ap + j) = wv;
    }
}

// ---------------- pass3: masked rows -> uniform mean of V -------------------
__global__ __launch_bounds__(64) void attn_pass3(
    const unsigned char* __restrict__ mask,
    const float* __restrict__ v, float* __restrict__ out)
{
    const int row = blockIdx.x * 64 + threadIdx.x;   // b*L + i
    const bool m = mask[row] != 0;
    if (!__syncthreads_or(m)) return;                // fast path: no masked rows
    if (!m) return;
    const int b = row >> 12;
    const float* vb = v + (size_t)b * LL * DD;
    for (int d = 0; d < DD; d++) {
        float s = 0.f;
        for (int kk = 0; kk < LL; kk++) s += vb[(size_t)kk * DD + d];
        out[(size_t)row * DD + d] = s * (1.0f / (float)LL);
    }
}

extern "C" void kernel_launch(void* const* d_in, const int* in_sizes, int n_in,
                              void* d_out, int out_size)
{
    (void)in_sizes; (void)n_in; (void)out_size;
    const float* q = (const float*)d_in[0];
    const float* k = (const float*)d_in[1];
    const float* v = (const float*)d_in[2];
    const unsigned char* mask = (const unsigned char*)d_in[3];

    float* out = (float*)d_out;
    float* attn = out + (size_t)BB * LL * DD;

    cudaFuncSetAttribute(attn_pass1, cudaFuncAttributeMaxDynamicSharedMemorySize, SMEM_TOTAL);

    const int NCONV = (int)(3 * (size_t)BB * LL * DD / 8 / 256);  // 6144 blocks
    convert_h<<<NCONV, 256>>>(q, k, v);
    attn_pass1<<<dim3(NQT, BB), 256, SMEM_TOTAL>>>(mask, out);
    attn_pass2<<<BB * LL, 256>>>(mask, attn);
    attn_pass3<<<BB * LL / 64, 64>>>(mask, v, out);
}